// round 2
// baseline (speedup 1.0000x reference)
#include <cuda_runtime.h>
#include <cuda_bf16.h>

// Problem constants
#define NN   4096
#define DD   2048
#define CC   128
#define D4   (DD/4)        // 512 float4 per row
#define KSLICES 8
#define KPER    (DD/KSLICES)   // 256 k per slice
#define KK4     (KPER/4)       // 64 float4 k-steps per slice

// ---------------- device scratch (no allocation allowed) ----------------
__device__ int   g_idx[CC * NN];        // per-class row lists (stride NN)
__device__ int   g_cnt[CC];
__device__ float g_CR [CC * DD];        // class means modal1  [c][k]
__device__ float g_CT [CC * DD];        // class means modal2  [c][k]
__device__ float g_CMt[DD * CC];        // 0.5*(CR+CT) transposed [k][c]
__device__ float g_nR[CC], g_nT[CC], g_nM[CC];
__device__ float g_P[KSLICES][2][CC * CC];  // Gram K-partials (fixed slots)

// ---------------- K0: deterministic per-class index lists ----------------
__global__ void k_classlist(const int* __restrict__ targets) {
    int c   = blockIdx.x;
    int tid = threadIdx.x;
    __shared__ int s_warp[8];
    __shared__ int s_base;
    if (tid == 0) s_base = 0;
    __syncthreads();
    for (int chunk = 0; chunk < NN; chunk += 256) {
        int t = targets[chunk + tid];
        bool flag = (t == c);
        unsigned mask = __ballot_sync(0xffffffffu, flag);
        int lane = tid & 31, warp = tid >> 5;
        int wpos = __popc(mask & ((1u << lane) - 1u));
        if (lane == 0) s_warp[warp] = __popc(mask);
        __syncthreads();
        int prefix = 0, total = 0;
        #pragma unroll
        for (int w = 0; w < 8; w++) {
            int v = s_warp[w];
            if (w < warp) prefix += v;
            total += v;
        }
        if (flag) g_idx[c * NN + s_base + prefix + wpos] = chunk + tid;
        __syncthreads();
        if (tid == 0) s_base += total;
        __syncthreads();
    }
    if (tid == 0) g_cnt[c] = s_base;
}

// ---------------- K1: per-class means (the 64MB read) ----------------
// grid (CC, 2), 256 threads; each thread owns one float4 column group.
__global__ void k_means(const float* __restrict__ m1, const float* __restrict__ m2) {
    int c    = blockIdx.x;
    int col4 = blockIdx.y * 256 + threadIdx.x;   // 0..511
    int cnt  = g_cnt[c];
    if (cnt > NN) cnt = NN;

    __shared__ int s_idx[NN];
    for (int i = threadIdx.x; i < cnt; i += 256) s_idx[i] = g_idx[c * NN + i];
    __syncthreads();

    const float4* __restrict__ m1v = (const float4*)m1;
    const float4* __restrict__ m2v = (const float4*)m2;

    float4 sR = make_float4(0.f, 0.f, 0.f, 0.f);
    float4 sT = make_float4(0.f, 0.f, 0.f, 0.f);
    int k = 0;
    for (; k + 4 <= cnt; k += 4) {
        #pragma unroll
        for (int u = 0; u < 4; u++) {
            int r = s_idx[k + u];
            float4 a = m1v[r * D4 + col4];
            float4 b = m2v[r * D4 + col4];
            sR.x += a.x; sR.y += a.y; sR.z += a.z; sR.w += a.w;
            sT.x += b.x; sT.y += b.y; sT.z += b.z; sT.w += b.w;
        }
    }
    for (; k < cnt; k++) {
        int r = s_idx[k];
        float4 a = m1v[r * D4 + col4];
        float4 b = m2v[r * D4 + col4];
        sR.x += a.x; sR.y += a.y; sR.z += a.z; sR.w += a.w;
        sT.x += b.x; sT.y += b.y; sT.z += b.z; sT.w += b.w;
    }

    float inv = 1.0f / (float)(cnt > 0 ? cnt : 1);
    float4 mr = make_float4(sR.x * inv, sR.y * inv, sR.z * inv, sR.w * inv);
    float4 mt = make_float4(sT.x * inv, sT.y * inv, sT.z * inv, sT.w * inv);
    float4 mm = make_float4(0.5f * (mr.x + mt.x), 0.5f * (mr.y + mt.y),
                            0.5f * (mr.z + mt.z), 0.5f * (mr.w + mt.w));

    ((float4*)g_CR)[c * D4 + col4] = mr;
    ((float4*)g_CT)[c * D4 + col4] = mt;
    int kb = col4 * 4;
    g_CMt[(kb + 0) * CC + c] = mm.x;
    g_CMt[(kb + 1) * CC + c] = mm.y;
    g_CMt[(kb + 2) * CC + c] = mm.z;
    g_CMt[(kb + 3) * CC + c] = mm.w;
}

// ---------------- K1b: per-class squared norms ----------------
__global__ void k_norms() {
    int c = blockIdx.x, tid = threadIdx.x;
    const float4* cr = (const float4*)(g_CR + c * DD);
    const float4* ct = (const float4*)(g_CT + c * DD);
    float aR = 0.f, aT = 0.f, aM = 0.f;
    for (int i = tid; i < D4; i += 256) {
        float4 r = cr[i], t = ct[i];
        aR += r.x * r.x + r.y * r.y + r.z * r.z + r.w * r.w;
        aT += t.x * t.x + t.y * t.y + t.z * t.z + t.w * t.w;
        float mx = 0.5f * (r.x + t.x), my = 0.5f * (r.y + t.y);
        float mz = 0.5f * (r.z + t.z), mw = 0.5f * (r.w + t.w);
        aM += mx * mx + my * my + mz * mz + mw * mw;
    }
    __shared__ float sR[256], sT[256], sM[256];
    sR[tid] = aR; sT[tid] = aT; sM[tid] = aM;
    __syncthreads();
    for (int s = 128; s > 0; s >>= 1) {
        if (tid < s) { sR[tid] += sR[tid + s]; sT[tid] += sT[tid + s]; sM[tid] += sM[tid + s]; }
        __syncthreads();
    }
    if (tid == 0) { g_nR[c] = sR[0]; g_nT[c] = sT[0]; g_nM[c] = sM[0]; }
}

// ---------------- K2: class Grams, K-split into fixed partial slots ----------------
// grid (16 a-tiles, KSLICES), 256 threads = 8 warps.
// warp -> one a; lane -> 4 b's (float4 from transposed CMt). FFMA-bound.
__global__ void k_gram() {
    int w = threadIdx.x >> 5, lane = threadIdx.x & 31;
    int a  = blockIdx.x * 8 + w;
    int ks = blockIdx.y;
    int kbase = ks * KPER;

    const float4* __restrict__ cr4  = (const float4*)(g_CR + a * DD + kbase);
    const float4* __restrict__ ct4  = (const float4*)(g_CT + a * DD + kbase);
    const float4* __restrict__ cmt4 = (const float4*)g_CMt;   // row k = 32 float4 of b

    float4 acc1 = make_float4(0.f, 0.f, 0.f, 0.f);
    float4 acc2 = make_float4(0.f, 0.f, 0.f, 0.f);

    #pragma unroll 4
    for (int kk = 0; kk < KK4; kk++) {
        float4 ar = cr4[kk];
        float4 at = ct4[kk];
        int krow = kbase + kk * 4;
        float4 b0 = cmt4[(krow + 0) * 32 + lane];
        float4 b1 = cmt4[(krow + 1) * 32 + lane];
        float4 b2 = cmt4[(krow + 2) * 32 + lane];
        float4 b3 = cmt4[(krow + 3) * 32 + lane];

        acc1.x += ar.x * b0.x; acc1.y += ar.x * b0.y; acc1.z += ar.x * b0.z; acc1.w += ar.x * b0.w;
        acc1.x += ar.y * b1.x; acc1.y += ar.y * b1.y; acc1.z += ar.y * b1.z; acc1.w += ar.y * b1.w;
        acc1.x += ar.z * b2.x; acc1.y += ar.z * b2.y; acc1.z += ar.z * b2.z; acc1.w += ar.z * b2.w;
        acc1.x += ar.w * b3.x; acc1.y += ar.w * b3.y; acc1.z += ar.w * b3.z; acc1.w += ar.w * b3.w;

        acc2.x += at.x * b0.x; acc2.y += at.x * b0.y; acc2.z += at.x * b0.z; acc2.w += at.x * b0.w;
        acc2.x += at.y * b1.x; acc2.y += at.y * b1.y; acc2.z += at.y * b1.z; acc2.w += at.y * b1.w;
        acc2.x += at.z * b2.x; acc2.y += at.z * b2.y; acc2.z += at.z * b2.z; acc2.w += at.z * b2.w;
        acc2.x += at.w * b3.x; acc2.y += at.w * b3.y; acc2.z += at.w * b3.z; acc2.w += at.w * b3.w;
    }

    ((float4*)(&g_P[ks][0][a * CC]))[lane] = acc1;
    ((float4*)(&g_P[ks][1][a * CC]))[lane] = acc2;
}

// ---------------- K3: final reduction over 128x128 class pairs ----------------
__global__ void k_loss(float* __restrict__ out) {
    int tid = threadIdx.x;   // 256
    float acc = 0.f;
    // q indexes groups of 4 consecutive b's: q in [0, 128*32)
    for (int q = tid; q < CC * 32; q += 256) {
        int a  = q >> 5;
        int b0 = (q & 31) * 4;
        float4 G1 = make_float4(0.f, 0.f, 0.f, 0.f);
        float4 G2 = make_float4(0.f, 0.f, 0.f, 0.f);
        #pragma unroll
        for (int ks = 0; ks < KSLICES; ks++) {
            float4 p1 = ((const float4*)g_P[ks][0])[q];
            float4 p2 = ((const float4*)g_P[ks][1])[q];
            G1.x += p1.x; G1.y += p1.y; G1.z += p1.z; G1.w += p1.w;
            G2.x += p2.x; G2.y += p2.y; G2.z += p2.z; G2.w += p2.w;
        }
        float na_R = g_nR[a], na_T = g_nT[a];
        float wa = (float)g_cnt[a];
        float g1[4] = {G1.x, G1.y, G1.z, G1.w};
        float g2[4] = {G2.x, G2.y, G2.z, G2.w};
        #pragma unroll
        for (int j = 0; j < 4; j++) {
            int b = b0 + j;
            float nM  = g_nM[b];
            float sq1 = fmaxf(na_R + nM - 2.f * g1[j], 1e-12f);
            float sq2 = fmaxf(na_T + nM - 2.f * g2[j], 1e-12f);
            float wgt = wa * (float)g_cnt[b];
            float term;
            if (a == b) {
                // label==1: contribution is dist^2 == clamped squared distance
                term = sq1 + sq2;
            } else {
                // label==0: relu(margin - sqrt(sqrt(sq)+1e-10))^2, usually 0
                term = 0.f;
                if (sq1 < 0.0625f) {   // only then can 0.5 - dd1 be > 0
                    float dd1 = sqrtf(sqrtf(sq1) + 1e-10f);
                    float r1  = fmaxf(0.5f - dd1, 0.f);
                    term += r1 * r1;
                }
                if (sq2 < 0.0625f) {
                    float dd2 = sqrtf(sqrtf(sq2) + 1e-10f);
                    float r2  = fmaxf(0.5f - dd2, 0.f);
                    term += r2 * r2;
                }
            }
            acc += wgt * term;
        }
    }
    __shared__ float sred[256];
    sred[tid] = acc;
    __syncthreads();
    for (int s = 128; s > 0; s >>= 1) {
        if (tid < s) sred[tid] += sred[tid + s];
        __syncthreads();
    }
    if (tid == 0) out[0] = sred[0] * (1.0f / ((float)NN * (float)NN));
}

// ---------------- launch ----------------
extern "C" void kernel_launch(void* const* d_in, const int* in_sizes, int n_in,
                              void* d_out, int out_size) {
    const float* m1 = (const float*)d_in[0];
    const float* m2 = (const float*)d_in[1];
    const int*   tg = (const int*)d_in[2];
    float* out = (float*)d_out;

    k_classlist<<<CC, 256>>>(tg);
    k_means<<<dim3(CC, 2), 256>>>(m1, m2);
    k_norms<<<CC, 256>>>();
    k_gram<<<dim3(CC / 8, KSLICES), 256>>>();
    k_loss<<<1, 256>>>(out);
}

// round 3
// speedup vs baseline: 2.3561x; 2.3561x over previous
#include <cuda_runtime.h>
#include <cuda_bf16.h>

// Problem constants
#define NN   4096
#define DD   2048
#define CC   128
#define D4   (DD/4)        // 512 float4 per row
#define MTOT 256           // stacked rows: 0..127 = CR, 128..255 = CT
#define MT   32            // gram m-tile per block
#define KS   32            // k slices
#define KSL  64            // k per slice (KS*KSL == DD)

// ---------------- device scratch (no allocation allowed) ----------------
__device__ int   g_idx[CC * NN];          // per-class row lists (stride NN)
__device__ int   g_cnt[CC];
__device__ float g_C  [MTOT * DD];        // class means: CR rows then CT rows
__device__ float g_CMt[DD * CC];          // 0.5*(CR+CT) transposed [k][c]
__device__ float g_nR[CC], g_nT[CC], g_nM[CC];
__device__ float g_P2[KS][MTOT * CC];     // Gram K-partials (4 MB, fixed slots)
__device__ float g_la[CC];                // per-class-row loss partials

// ---------------- K0: deterministic per-class index lists ----------------
__global__ void k_classlist(const int* __restrict__ targets) {
    int c   = blockIdx.x;
    int tid = threadIdx.x;
    __shared__ int s_warp[8];
    __shared__ int s_base;
    if (tid == 0) s_base = 0;
    __syncthreads();
    for (int chunk = 0; chunk < NN; chunk += 256) {
        int t = targets[chunk + tid];
        bool flag = (t == c);
        unsigned mask = __ballot_sync(0xffffffffu, flag);
        int lane = tid & 31, warp = tid >> 5;
        int wpos = __popc(mask & ((1u << lane) - 1u));
        if (lane == 0) s_warp[warp] = __popc(mask);
        __syncthreads();
        int prefix = 0, total = 0;
        #pragma unroll
        for (int w = 0; w < 8; w++) {
            int v = s_warp[w];
            if (w < warp) prefix += v;
            total += v;
        }
        if (flag) g_idx[c * NN + s_base + prefix + wpos] = chunk + tid;
        __syncthreads();
        if (tid == 0) s_base += total;
        __syncthreads();
    }
    if (tid == 0) g_cnt[c] = s_base;
}

// ---------------- K1: per-class means (the 64MB read) ----------------
// grid (CC, 2), 256 threads; each thread owns one float4 column group.
__global__ void k_means(const float* __restrict__ m1, const float* __restrict__ m2) {
    int c    = blockIdx.x;
    int col4 = blockIdx.y * 256 + threadIdx.x;   // 0..511
    int cnt  = g_cnt[c];
    if (cnt > NN) cnt = NN;

    __shared__ int s_idx[NN];
    for (int i = threadIdx.x; i < cnt; i += 256) s_idx[i] = g_idx[c * NN + i];
    __syncthreads();

    const float4* __restrict__ m1v = (const float4*)m1;
    const float4* __restrict__ m2v = (const float4*)m2;

    float4 sR = make_float4(0.f, 0.f, 0.f, 0.f);
    float4 sT = make_float4(0.f, 0.f, 0.f, 0.f);
    int k = 0;
    for (; k + 8 <= cnt; k += 8) {
        #pragma unroll
        for (int u = 0; u < 8; u++) {
            int r = s_idx[k + u];
            float4 a = m1v[r * D4 + col4];
            float4 b = m2v[r * D4 + col4];
            sR.x += a.x; sR.y += a.y; sR.z += a.z; sR.w += a.w;
            sT.x += b.x; sT.y += b.y; sT.z += b.z; sT.w += b.w;
        }
    }
    for (; k < cnt; k++) {
        int r = s_idx[k];
        float4 a = m1v[r * D4 + col4];
        float4 b = m2v[r * D4 + col4];
        sR.x += a.x; sR.y += a.y; sR.z += a.z; sR.w += a.w;
        sT.x += b.x; sT.y += b.y; sT.z += b.z; sT.w += b.w;
    }

    float inv = 1.0f / (float)(cnt > 0 ? cnt : 1);
    float4 mr = make_float4(sR.x * inv, sR.y * inv, sR.z * inv, sR.w * inv);
    float4 mt = make_float4(sT.x * inv, sT.y * inv, sT.z * inv, sT.w * inv);
    float4 mm = make_float4(0.5f * (mr.x + mt.x), 0.5f * (mr.y + mt.y),
                            0.5f * (mr.z + mt.z), 0.5f * (mr.w + mt.w));

    ((float4*)g_C)[c * D4 + col4]        = mr;     // CR row
    ((float4*)g_C)[(CC + c) * D4 + col4] = mt;     // CT row
    int kb = col4 * 4;
    g_CMt[(kb + 0) * CC + c] = mm.x;
    g_CMt[(kb + 1) * CC + c] = mm.y;
    g_CMt[(kb + 2) * CC + c] = mm.z;
    g_CMt[(kb + 3) * CC + c] = mm.w;
}

// ---------------- K1b: per-class squared norms ----------------
__global__ void k_norms() {
    int c = blockIdx.x, tid = threadIdx.x;
    const float4* cr = (const float4*)(g_C + c * DD);
    const float4* ct = (const float4*)(g_C + (CC + c) * DD);
    float aR = 0.f, aT = 0.f, aM = 0.f;
    for (int i = tid; i < D4; i += 256) {
        float4 r = cr[i], t = ct[i];
        aR += r.x * r.x + r.y * r.y + r.z * r.z + r.w * r.w;
        aT += t.x * t.x + t.y * t.y + t.z * t.z + t.w * t.w;
        float mx = 0.5f * (r.x + t.x), my = 0.5f * (r.y + t.y);
        float mz = 0.5f * (r.z + t.z), mw = 0.5f * (r.w + t.w);
        aM += mx * mx + my * my + mz * mz + mw * mw;
    }
    __shared__ float sR[256], sT[256], sM[256];
    sR[tid] = aR; sT[tid] = aT; sM[tid] = aM;
    __syncthreads();
    for (int s = 128; s > 0; s >>= 1) {
        if (tid < s) { sR[tid] += sR[tid + s]; sT[tid] += sT[tid + s]; sM[tid] += sM[tid + s]; }
        __syncthreads();
    }
    if (tid == 0) { g_nR[c] = sR[0]; g_nT[c] = sT[0]; g_nM[c] = sM[0]; }
}

// ---------------- K2: smem-tiled Gram: C[256x128] = A[256xK] * CMt ----------------
// grid (MTOT/MT=8, KS=32) = 256 blocks, 256 threads.
// Block computes a 32x128 tile over a K-slice of 64, writes to fixed partial slot.
__global__ void __launch_bounds__(256) k_gram() {
    __shared__ float  As[MT][KSL];            // 8 KB, [m][k]
    __shared__ float4 Bs[KSL * (CC / 4)];     // 32 KB, [k][n/4]

    int tid   = threadIdx.x;
    int m0    = blockIdx.x * MT;
    int kbase = blockIdx.y * KSL;

    // Load A tile: 32 rows x 64 floats = 512 float4 (2 per thread), coalesced.
    {
        const float4* __restrict__ src = (const float4*)g_C;
        #pragma unroll
        for (int i = 0; i < 2; i++) {
            int q  = tid * 2 + i;      // 0..511
            int r  = q >> 4;           // row 0..31
            int c4 = q & 15;           // float4 idx within 64-float slice
            float4 v = src[(m0 + r) * D4 + (kbase >> 2) + c4];
            ((float4*)&As[r][0])[c4] = v;
        }
    }
    // Load B tile: 64 k-rows x 128 floats = 2048 float4 (8 per thread), coalesced.
    {
        const float4* __restrict__ src = (const float4*)g_CMt;
        #pragma unroll
        for (int i = 0; i < 8; i++) {
            int q = i * 256 + tid;     // 0..2047 == k*32 + c4
            Bs[q] = src[kbase * (CC / 4) + q];
        }
    }
    __syncthreads();

    int tx = tid & 31;   // n-group: columns tx*4..tx*4+3
    int ty = tid >> 5;   // m-group (== warp id): rows ty*4..ty*4+3
    float a00=0.f,a01=0.f,a02=0.f,a03=0.f;
    float a10=0.f,a11=0.f,a12=0.f,a13=0.f;
    float a20=0.f,a21=0.f,a22=0.f,a23=0.f;
    float a30=0.f,a31=0.f,a32=0.f,a33=0.f;

    #pragma unroll 4
    for (int k = 0; k < KSL; k++) {
        float4 b = Bs[k * 32 + tx];            // conflict-free LDS.128
        float v0 = As[ty * 4 + 0][k];          // broadcast LDS.32
        float v1 = As[ty * 4 + 1][k];
        float v2 = As[ty * 4 + 2][k];
        float v3 = As[ty * 4 + 3][k];
        a00 += v0 * b.x; a01 += v0 * b.y; a02 += v0 * b.z; a03 += v0 * b.w;
        a10 += v1 * b.x; a11 += v1 * b.y; a12 += v1 * b.z; a13 += v1 * b.w;
        a20 += v2 * b.x; a21 += v2 * b.y; a22 += v2 * b.z; a23 += v2 * b.w;
        a30 += v3 * b.x; a31 += v3 * b.y; a32 += v3 * b.z; a33 += v3 * b.w;
    }

    float* __restrict__ dst = &g_P2[blockIdx.y][0];
    ((float4*)&dst[(m0 + ty * 4 + 0) * CC])[tx] = make_float4(a00, a01, a02, a03);
    ((float4*)&dst[(m0 + ty * 4 + 1) * CC])[tx] = make_float4(a10, a11, a12, a13);
    ((float4*)&dst[(m0 + ty * 4 + 2) * CC])[tx] = make_float4(a20, a21, a22, a23);
    ((float4*)&dst[(m0 + ty * 4 + 3) * CC])[tx] = make_float4(a30, a31, a32, a33);
}

// ---------------- K3a: per-class-row loss (128 blocks, deterministic) ----------------
__global__ void k_lossA() {
    int a   = blockIdx.x;
    int b   = threadIdx.x;      // 128 threads, one per b
    float G1 = 0.f, G2 = 0.f;
    #pragma unroll
    for (int ks = 0; ks < KS; ks++) {
        G1 += g_P2[ks][a * CC + b];           // CR row a . Cm_b
        G2 += g_P2[ks][(CC + a) * CC + b];    // CT row a . Cm_b
    }
    float nM  = g_nM[b];
    float sq1 = fmaxf(g_nR[a] + nM - 2.f * G1, 1e-12f);
    float sq2 = fmaxf(g_nT[a] + nM - 2.f * G2, 1e-12f);
    float wgt = (float)g_cnt[a] * (float)g_cnt[b];
    float term;
    if (a == b) {
        // label==1: d^2 == clamped squared distance
        term = sq1 + sq2;
    } else {
        // label==0: relu(0.5 - (sq)^(1/4))^2, nonzero only if sq < 0.5^4
        term = 0.f;
        if (sq1 < 0.0625f) {
            float dd1 = sqrtf(sqrtf(sq1) + 1e-10f);
            float r1  = fmaxf(0.5f - dd1, 0.f);
            term += r1 * r1;
        }
        if (sq2 < 0.0625f) {
            float dd2 = sqrtf(sqrtf(sq2) + 1e-10f);
            float r2  = fmaxf(0.5f - dd2, 0.f);
            term += r2 * r2;
        }
    }
    __shared__ float sred[128];
    sred[b] = wgt * term;
    __syncthreads();
    for (int s = 64; s > 0; s >>= 1) {
        if (b < s) sred[b] += sred[b + s];
        __syncthreads();
    }
    if (b == 0) g_la[a] = sred[0];
}

// ---------------- K3b: final 128-value reduce ----------------
__global__ void k_lossB(float* __restrict__ out) {
    int tid = threadIdx.x;   // 128
    __shared__ float sred[128];
    sred[tid] = g_la[tid];
    __syncthreads();
    for (int s = 64; s > 0; s >>= 1) {
        if (tid < s) sred[tid] += sred[tid + s];
        __syncthreads();
    }
    if (tid == 0) out[0] = sred[0] * (1.0f / ((float)NN * (float)NN));
}

// ---------------- launch ----------------
extern "C" void kernel_launch(void* const* d_in, const int* in_sizes, int n_in,
                              void* d_out, int out_size) {
    const float* m1 = (const float*)d_in[0];
    const float* m2 = (const float*)d_in[1];
    const int*   tg = (const int*)d_in[2];
    float* out = (float*)d_out;

    k_classlist<<<CC, 256>>>(tg);
    k_means<<<dim3(CC, 2), 256>>>(m1, m2);
    k_norms<<<CC, 256>>>();
    k_gram<<<dim3(MTOT / MT, KS), 256>>>();
    k_lossA<<<CC, 128>>>();
    k_lossB<<<1, 128>>>(out);
}

// round 5
// speedup vs baseline: 2.6609x; 1.1293x over previous
#include <cuda_runtime.h>

// Problem constants
#define NN   4096
#define DD   2048
#define CC   128
#define D4   (DD/4)          // 512 float4 per row
#define MTOT 256             // stacked rows: 0..127 = CR, 128..255 = CT
#define MT   64              // gram m-tile per block
#define KS   64              // k slices
#define KSL  32              // k per slice (KS*KSL == DD)

// ---------------- device scratch (no allocation allowed) ----------------
__device__ int   g_cnt[CC];
__device__ float g_C  [MTOT * DD];       // class means [m][k]: CR rows then CT rows
__device__ float g_Ct [DD * MTOT];       // transposed [k][m]   (2 MB)
__device__ float g_CMt[DD * CC];         // 0.5*(CR+CT) [k][c]  (1 MB)
__device__ float g_nPart[4][3][CC];      // per-col-quarter norm partials (R,T,M)
__device__ float g_P2[KS][MTOT * CC];    // Gram K-partials, fixed slots (8 MB)
__device__ float g_la[CC];               // per-class-row loss partials
__device__ int   g_ctr = 0;              // last-block counter (self-resetting)

// ---------------- K1: fused classlist-scan + per-class means + norm partials ---
// grid (CC, 4), 128 threads. Block (c,y): builds class-c row list via
// deterministic ballot scan, gathers its column quarter, writes means and
// norm partials. Carries the mandatory 64MB read.
__global__ void __launch_bounds__(128) k_means(const float* __restrict__ m1,
                                               const float* __restrict__ m2,
                                               const int*   __restrict__ targets) {
    int c = blockIdx.x, y = blockIdx.y, tid = threadIdx.x;
    int lane = tid & 31, warp = tid >> 5;

    __shared__ int s_idx[NN];     // 16 KB
    __shared__ int s_w[4];
    __shared__ int s_base;
    if (tid == 0) s_base = 0;
    __syncthreads();

    // deterministic ballot scan over targets
    for (int chunk = 0; chunk < NN; chunk += 128) {
        int t = targets[chunk + tid];
        bool flag = (t == c);
        unsigned mask = __ballot_sync(0xffffffffu, flag);
        int wpos = __popc(mask & ((1u << lane) - 1u));
        if (lane == 0) s_w[warp] = __popc(mask);
        __syncthreads();
        int prefix = 0, total = 0;
        #pragma unroll
        for (int w = 0; w < 4; w++) { int v = s_w[w]; if (w < warp) prefix += v; total += v; }
        if (flag) s_idx[s_base + prefix + wpos] = chunk + tid;
        __syncthreads();
        if (tid == 0) s_base += total;
        __syncthreads();
    }
    int cnt = s_base;
    if (cnt > NN) cnt = NN;

    // gather: this block owns 128 consecutive float4 columns
    int col4 = y * 128 + tid;     // 0..511
    const float4* __restrict__ m1v = (const float4*)m1;
    const float4* __restrict__ m2v = (const float4*)m2;

    float4 sR = make_float4(0.f, 0.f, 0.f, 0.f);
    float4 sT = make_float4(0.f, 0.f, 0.f, 0.f);
    int k = 0;
    for (; k + 8 <= cnt; k += 8) {
        #pragma unroll
        for (int u = 0; u < 8; u++) {
            int r = s_idx[k + u];
            float4 a = m1v[r * D4 + col4];
            float4 b = m2v[r * D4 + col4];
            sR.x += a.x; sR.y += a.y; sR.z += a.z; sR.w += a.w;
            sT.x += b.x; sT.y += b.y; sT.z += b.z; sT.w += b.w;
        }
    }
    for (; k < cnt; k++) {
        int r = s_idx[k];
        float4 a = m1v[r * D4 + col4];
        float4 b = m2v[r * D4 + col4];
        sR.x += a.x; sR.y += a.y; sR.z += a.z; sR.w += a.w;
        sT.x += b.x; sT.y += b.y; sT.z += b.z; sT.w += b.w;
    }

    float inv = 1.0f / (float)(cnt > 0 ? cnt : 1);
    float4 mr = make_float4(sR.x * inv, sR.y * inv, sR.z * inv, sR.w * inv);
    float4 mt = make_float4(sT.x * inv, sT.y * inv, sT.z * inv, sT.w * inv);
    float4 mm = make_float4(0.5f * (mr.x + mt.x), 0.5f * (mr.y + mt.y),
                            0.5f * (mr.z + mt.z), 0.5f * (mr.w + mt.w));

    ((float4*)g_C)[c * D4 + col4]        = mr;
    ((float4*)g_C)[(CC + c) * D4 + col4] = mt;

    // norm partials over this column quarter (fixed-tree reduce)
    float pR = mr.x * mr.x + mr.y * mr.y + mr.z * mr.z + mr.w * mr.w;
    float pT = mt.x * mt.x + mt.y * mt.y + mt.z * mt.z + mt.w * mt.w;
    float pM = mm.x * mm.x + mm.y * mm.y + mm.z * mm.z + mm.w * mm.w;
    __shared__ float r0[128], r1[128], r2[128];
    r0[tid] = pR; r1[tid] = pT; r2[tid] = pM;
    __syncthreads();
    for (int s = 64; s > 0; s >>= 1) {
        if (tid < s) { r0[tid] += r0[tid + s]; r1[tid] += r1[tid + s]; r2[tid] += r2[tid + s]; }
        __syncthreads();
    }
    if (tid == 0) {
        g_nPart[y][0][c] = r0[0];
        g_nPart[y][1][c] = r1[0];
        g_nPart[y][2][c] = r2[0];
        if (y == 0) g_cnt[c] = cnt;
    }
}

// ---------------- K2: paired-tile transpose; also emits CMt = 0.5(CR+CT) ------
// grid (DD/32 = 64 k-tiles, CC/32 = 4 m-pair-tiles), 256 threads.
__global__ void __launch_bounds__(256) k_T() {
    __shared__ float sR[32][33];
    __shared__ float sT[32][33];
    int kt = blockIdx.x, mt = blockIdx.y, tid = threadIdx.x;
    int mbase = mt * 32;

    const float4* __restrict__ c4 = (const float4*)g_C;
    int r  = tid >> 3;     // 0..31 (row within tile)
    int q4 = tid & 7;      // 0..7  (float4 within 32-float k window)
    float4 vR = c4[(mbase + r) * D4 + kt * 8 + q4];
    float4 vT = c4[(128 + mbase + r) * D4 + kt * 8 + q4];
    sR[r][q4 * 4 + 0] = vR.x; sR[r][q4 * 4 + 1] = vR.y;
    sR[r][q4 * 4 + 2] = vR.z; sR[r][q4 * 4 + 3] = vR.w;
    sT[r][q4 * 4 + 0] = vT.x; sT[r][q4 * 4 + 1] = vT.y;
    sT[r][q4 * 4 + 2] = vT.z; sT[r][q4 * 4 + 3] = vT.w;
    __syncthreads();

    int kk = tid >> 3;     // 0..31 (k within tile)
    int m4 = tid & 7;      // 0..7  (float4 of m)
    float4 wR = make_float4(sR[m4 * 4 + 0][kk], sR[m4 * 4 + 1][kk],
                            sR[m4 * 4 + 2][kk], sR[m4 * 4 + 3][kk]);
    float4 wT = make_float4(sT[m4 * 4 + 0][kk], sT[m4 * 4 + 1][kk],
                            sT[m4 * 4 + 2][kk], sT[m4 * 4 + 3][kk]);
    float4 wM = make_float4(0.5f * (wR.x + wT.x), 0.5f * (wR.y + wT.y),
                            0.5f * (wR.z + wT.z), 0.5f * (wR.w + wT.w));
    int krow = kt * 32 + kk;
    ((float4*)g_Ct)[krow * (MTOT / 4) + (mbase >> 2) + m4]         = wR;
    ((float4*)g_Ct)[krow * (MTOT / 4) + ((128 + mbase) >> 2) + m4] = wT;
    ((float4*)g_CMt)[krow * (CC / 4) + (mbase >> 2) + m4]          = wM;
}

// ---------------- K3: smem-tiled Gram: [256x128] = [CR;CT] * CmT --------------
// grid (MTOT/MT = 4, KS = 64) = 256 blocks, 256 threads. 8x4 register tile.
// All smem fills are direct coalesced float4 copies (operands pre-transposed).
__global__ void __launch_bounds__(256) k_gram() {
    __shared__ float4 As4[KSL][17];    // [k][16 used] (pad kills STS conflicts)
    __shared__ float4 Bs4[KSL][33];    // [k][32 used]

    int tid = threadIdx.x;
    int m0  = blockIdx.x * MT;
    int kb  = blockIdx.y * KSL;

    const float4* __restrict__ ct4 = (const float4*)g_Ct;
    #pragma unroll
    for (int i = 0; i < 2; i++) {
        int idx = tid + i * 256;            // 0..511
        int k = idx >> 4, j = idx & 15;
        As4[k][j] = ct4[(kb + k) * (MTOT / 4) + (m0 >> 2) + j];
    }
    const float4* __restrict__ cm4 = (const float4*)g_CMt;
    #pragma unroll
    for (int i = 0; i < 4; i++) {
        int idx = tid + i * 256;            // 0..1023
        int k = idx >> 5, q = idx & 31;
        Bs4[k][q] = cm4[(kb + k) * (CC / 4) + q];
    }
    __syncthreads();

    int tx = tid & 31;     // col group: columns tx*4..+3
    int ty = tid >> 5;     // row group: rows ty*8..+7 (uniform per warp -> LDS broadcast)

    float4 acc[8];
    #pragma unroll
    for (int rr = 0; rr < 8; rr++) acc[rr] = make_float4(0.f, 0.f, 0.f, 0.f);

    #pragma unroll 8
    for (int k = 0; k < KSL; k++) {
        float4 b  = Bs4[k][tx];
        float4 a0 = As4[k][ty * 2];
        float4 a1 = As4[k][ty * 2 + 1];
        float av[8] = {a0.x, a0.y, a0.z, a0.w, a1.x, a1.y, a1.z, a1.w};
        #pragma unroll
        for (int rr = 0; rr < 8; rr++) {
            acc[rr].x += av[rr] * b.x;
            acc[rr].y += av[rr] * b.y;
            acc[rr].z += av[rr] * b.z;
            acc[rr].w += av[rr] * b.w;
        }
    }

    float4* __restrict__ dst = (float4*)(&g_P2[blockIdx.y][0]);
    #pragma unroll
    for (int rr = 0; rr < 8; rr++)
        dst[(m0 + ty * 8 + rr) * (CC / 4) + tx] = acc[rr];
}

// ---------------- K4: loss over class pairs + last-block final reduce ---------
__global__ void __launch_bounds__(128) k_loss(float* __restrict__ out) {
    int a = blockIdx.x, b = threadIdx.x;    // 128 threads, one per b

    float G1 = 0.f, G2 = 0.f;
    #pragma unroll 8
    for (int ks = 0; ks < KS; ks++) {
        G1 += g_P2[ks][a * CC + b];
        G2 += g_P2[ks][(CC + a) * CC + b];
    }
    float nRa = 0.f, nTa = 0.f, nMb = 0.f;
    #pragma unroll
    for (int y = 0; y < 4; y++) {
        nRa += g_nPart[y][0][a];
        nTa += g_nPart[y][1][a];
        nMb += g_nPart[y][2][b];
    }

    float sq1 = fmaxf(nRa + nMb - 2.f * G1, 1e-12f);
    float sq2 = fmaxf(nTa + nMb - 2.f * G2, 1e-12f);
    float wgt = (float)g_cnt[a] * (float)g_cnt[b];
    float term;
    if (a == b) {
        // label==1: d^2 == clamped squared distance
        term = sq1 + sq2;
    } else {
        // label==0: relu(0.5 - sq^(1/4))^2, nonzero only if sq < 0.5^4
        term = 0.f;
        if (sq1 < 0.0625f) {
            float dd1 = sqrtf(sqrtf(sq1) + 1e-10f);
            float r1  = fmaxf(0.5f - dd1, 0.f);
            term += r1 * r1;
        }
        if (sq2 < 0.0625f) {
            float dd2 = sqrtf(sqrtf(sq2) + 1e-10f);
            float r2  = fmaxf(0.5f - dd2, 0.f);
            term += r2 * r2;
        }
    }

    __shared__ float sred[128];
    sred[b] = wgt * term;
    __syncthreads();
    for (int s = 64; s > 0; s >>= 1) {
        if (b < s) sred[b] += sred[b + s];
        __syncthreads();
    }
    if (b == 0) g_la[a] = sred[0];

    // last-block final reduce (threadFenceReduction pattern; deterministic)
    __shared__ int s_last;
    if (b == 0) {
        __threadfence();
        int t = atomicAdd(&g_ctr, 1);
        s_last = (t == CC - 1) ? 1 : 0;
    }
    __syncthreads();
    if (s_last) {
        sred[b] = g_la[b];
        __syncthreads();
        for (int s = 64; s > 0; s >>= 1) {
            if (b < s) sred[b] += sred[b + s];
            __syncthreads();
        }
        if (b == 0) {
            out[0] = sred[0] * (1.0f / ((float)NN * (float)NN));
            g_ctr = 0;   // reset for next graph replay
        }
    }
}

// ---------------- launch ----------------
extern "C" void kernel_launch(void* const* d_in, const int* in_sizes, int n_in,
                              void* d_out, int out_size) {
    const float* m1 = (const float*)d_in[0];
    const float* m2 = (const float*)d_in[1];
    const int*   tg = (const int*)d_in[2];
    float* out = (float*)d_out;

    k_means<<<dim3(CC, 4), 128>>>(m1, m2, tg);
    k_T<<<dim3(DD / 32, CC / 32), 256>>>();
    k_gram<<<dim3(MTOT / MT, KS), 256>>>();
    k_loss<<<CC, 128>>>(out);
}

// round 6
// speedup vs baseline: 3.0754x; 1.1558x over previous
#include <cuda_runtime.h>

// Problem constants
#define NN   4096
#define DD   2048
#define CC   128
#define D4   (DD/4)          // 512 float4 per row
#define MTOT 256             // stacked rows: 0..127 = CR, 128..255 = CT
#define MT   32              // gram m-tile per block
#define KS   32              // k slices
#define KSL  64              // k per slice (KS*KSL == DD)

// ---------------- device scratch (no allocation allowed) ----------------
__device__ int   g_cnt[CC];
__device__ float g_C  [MTOT * DD];       // class means [m][k]: CR rows then CT rows
__device__ float g_Ct [DD * MTOT];       // transposed [k][m]   (2 MB)
__device__ float g_CMt[DD * CC];         // 0.5*(CR+CT) [k][c]  (1 MB)
__device__ float g_nPart[4][3][CC];      // per-col-quarter norm partials (R,T,M)
__device__ float g_P2[KS][MTOT * CC];    // Gram K-partials, fixed slots (4 MB)
__device__ float g_la[CC];               // per-class-row loss partials
__device__ int   g_ctr = 0;              // last-block counter (self-resetting)

// ---------------- f32x2 helpers (FFMA2 path) ----------------
__device__ __forceinline__ unsigned long long pack2(float x, float y) {
    unsigned long long r;
    asm("mov.b64 %0, {%1, %2};" : "=l"(r) : "f"(x), "f"(y));
    return r;
}
__device__ __forceinline__ unsigned long long fma2(unsigned long long a,
                                                   unsigned long long b,
                                                   unsigned long long c) {
    unsigned long long d;
    asm("fma.rn.f32x2 %0, %1, %2, %3;" : "=l"(d) : "l"(a), "l"(b), "l"(c));
    return d;
}
__device__ __forceinline__ float2 unpack2(unsigned long long v) {
    float2 f;
    asm("mov.b64 {%0, %1}, %2;" : "=f"(f.x), "=f"(f.y) : "l"(v));
    return f;
}

// ---------------- K1: fused warp-scan classlist + per-class means + norms -----
// grid (CC, 4), 128 threads. Warp-local scans (no block syncs in the scan loop),
// then deterministic concat. Carries the mandatory 64MB read.
__global__ void __launch_bounds__(128) k_means(const float* __restrict__ m1,
                                               const float* __restrict__ m2,
                                               const int*   __restrict__ targets) {
    int c = blockIdx.x, y = blockIdx.y, tid = threadIdx.x;
    int lane = tid & 31, warp = tid >> 5;

    __shared__ int s_list[4][1024];   // per-warp candidate lists (worst-case safe)
    __shared__ int s_cnt[4];
    __shared__ int s_idx[NN];

    // warp w scans targets[w*1024 .. +1024) independently — no block barriers
    {
        int base = warp * 1024;
        int cntw = 0;
        unsigned lt = (1u << lane) - 1u;
        #pragma unroll 4
        for (int j = 0; j < 32; j++) {
            int i = base + j * 32 + lane;
            int t = targets[i];
            bool flag = (t == c);
            unsigned mask = __ballot_sync(0xffffffffu, flag);
            if (flag) s_list[warp][cntw + __popc(mask & lt)] = i;
            cntw += __popc(mask);
        }
        if (lane == 0) s_cnt[warp] = cntw;
    }
    __syncthreads();

    int cw0 = s_cnt[0], cw1 = s_cnt[1], cw2 = s_cnt[2], cw3 = s_cnt[3];
    int cnt = cw0 + cw1 + cw2 + cw3;
    if (cnt > NN) cnt = NN;
    {   // deterministic concat: warp w copies its list to its fixed offset
        int off = (warp > 0 ? cw0 : 0) + (warp > 1 ? cw1 : 0) + (warp > 2 ? cw2 : 0);
        int n = s_cnt[warp];
        for (int i = lane; i < n; i += 32) s_idx[off + i] = s_list[warp][i];
    }
    __syncthreads();

    // gather: this block owns 128 consecutive float4 columns
    int col4 = y * 128 + tid;     // 0..511
    const float4* __restrict__ m1v = (const float4*)m1;
    const float4* __restrict__ m2v = (const float4*)m2;

    float4 sR = make_float4(0.f, 0.f, 0.f, 0.f);
    float4 sT = make_float4(0.f, 0.f, 0.f, 0.f);
    int k = 0;
    for (; k + 8 <= cnt; k += 8) {
        #pragma unroll
        for (int u = 0; u < 8; u++) {
            int r = s_idx[k + u];
            float4 a = m1v[r * D4 + col4];
            float4 b = m2v[r * D4 + col4];
            sR.x += a.x; sR.y += a.y; sR.z += a.z; sR.w += a.w;
            sT.x += b.x; sT.y += b.y; sT.z += b.z; sT.w += b.w;
        }
    }
    for (; k < cnt; k++) {
        int r = s_idx[k];
        float4 a = m1v[r * D4 + col4];
        float4 b = m2v[r * D4 + col4];
        sR.x += a.x; sR.y += a.y; sR.z += a.z; sR.w += a.w;
        sT.x += b.x; sT.y += b.y; sT.z += b.z; sT.w += b.w;
    }

    float inv = 1.0f / (float)(cnt > 0 ? cnt : 1);
    float4 mr = make_float4(sR.x * inv, sR.y * inv, sR.z * inv, sR.w * inv);
    float4 mt = make_float4(sT.x * inv, sT.y * inv, sT.z * inv, sT.w * inv);
    float4 mm = make_float4(0.5f * (mr.x + mt.x), 0.5f * (mr.y + mt.y),
                            0.5f * (mr.z + mt.z), 0.5f * (mr.w + mt.w));

    ((float4*)g_C)[c * D4 + col4]        = mr;
    ((float4*)g_C)[(CC + c) * D4 + col4] = mt;

    // norm partials over this column quarter (fixed-tree reduce)
    float pR = mr.x * mr.x + mr.y * mr.y + mr.z * mr.z + mr.w * mr.w;
    float pT = mt.x * mt.x + mt.y * mt.y + mt.z * mt.z + mt.w * mt.w;
    float pM = mm.x * mm.x + mm.y * mm.y + mm.z * mm.z + mm.w * mm.w;
    __shared__ float r0[128], r1[128], r2[128];
    r0[tid] = pR; r1[tid] = pT; r2[tid] = pM;
    __syncthreads();
    for (int s = 64; s > 0; s >>= 1) {
        if (tid < s) { r0[tid] += r0[tid + s]; r1[tid] += r1[tid + s]; r2[tid] += r2[tid + s]; }
        __syncthreads();
    }
    if (tid == 0) {
        g_nPart[y][0][c] = r0[0];
        g_nPart[y][1][c] = r1[0];
        g_nPart[y][2][c] = r2[0];
        if (y == 0) g_cnt[c] = cnt;
    }
}

// ---------------- K2: paired-tile transpose; also emits CMt = 0.5(CR+CT) ------
// grid (DD/32 = 64 k-tiles, CC/32 = 4 m-pair-tiles), 256 threads.
__global__ void __launch_bounds__(256) k_T() {
    __shared__ float sR[32][33];
    __shared__ float sT[32][33];
    int kt = blockIdx.x, mt = blockIdx.y, tid = threadIdx.x;
    int mbase = mt * 32;

    const float4* __restrict__ c4 = (const float4*)g_C;
    int r  = tid >> 3;     // 0..31 (row within tile)
    int q4 = tid & 7;      // 0..7  (float4 within 32-float k window)
    float4 vR = c4[(mbase + r) * D4 + kt * 8 + q4];
    float4 vT = c4[(128 + mbase + r) * D4 + kt * 8 + q4];
    sR[r][q4 * 4 + 0] = vR.x; sR[r][q4 * 4 + 1] = vR.y;
    sR[r][q4 * 4 + 2] = vR.z; sR[r][q4 * 4 + 3] = vR.w;
    sT[r][q4 * 4 + 0] = vT.x; sT[r][q4 * 4 + 1] = vT.y;
    sT[r][q4 * 4 + 2] = vT.z; sT[r][q4 * 4 + 3] = vT.w;
    __syncthreads();

    int kk = tid >> 3;     // 0..31 (k within tile)
    int m4 = tid & 7;      // 0..7  (float4 of m)
    float4 wR = make_float4(sR[m4 * 4 + 0][kk], sR[m4 * 4 + 1][kk],
                            sR[m4 * 4 + 2][kk], sR[m4 * 4 + 3][kk]);
    float4 wT = make_float4(sT[m4 * 4 + 0][kk], sT[m4 * 4 + 1][kk],
                            sT[m4 * 4 + 2][kk], sT[m4 * 4 + 3][kk]);
    float4 wM = make_float4(0.5f * (wR.x + wT.x), 0.5f * (wR.y + wT.y),
                            0.5f * (wR.z + wT.z), 0.5f * (wR.w + wT.w));
    int krow = kt * 32 + kk;
    ((float4*)g_Ct)[krow * (MTOT / 4) + (mbase >> 2) + m4]         = wR;
    ((float4*)g_Ct)[krow * (MTOT / 4) + ((128 + mbase) >> 2) + m4] = wT;
    ((float4*)g_CMt)[krow * (CC / 4) + (mbase >> 2) + m4]          = wM;
}

// ---------------- K3: smem-tiled Gram with FFMA2: [256x128] = [CR;CT] * CmT ---
// grid (MTOT/MT = 8, KS = 32) = 256 blocks, 256 threads. 4x4 tile per thread,
// rows paired into f32x2 accumulators.
__global__ void __launch_bounds__(256) k_gram() {
    __shared__ float4 As4[KSL][9];     // [k][8 used], rows m0..m0+31
    __shared__ float4 Bs4[KSL][33];    // [k][32 used], all 128 cols

    int tid = threadIdx.x;
    int m0  = blockIdx.x * MT;
    int kb  = blockIdx.y * KSL;

    const float4* __restrict__ ct4 = (const float4*)g_Ct;
    #pragma unroll
    for (int i = 0; i < 2; i++) {
        int idx = tid + i * 256;            // 0..511
        int k = idx >> 3, j = idx & 7;
        As4[k][j] = ct4[(kb + k) * (MTOT / 4) + (m0 >> 2) + j];
    }
    const float4* __restrict__ cm4 = (const float4*)g_CMt;
    #pragma unroll
    for (int i = 0; i < 8; i++) {
        int idx = tid + i * 256;            // 0..2047
        int k = idx >> 5, q = idx & 31;
        Bs4[k][q] = cm4[(kb + k) * (CC / 4) + q];
    }
    __syncthreads();

    int tx = tid & 31;     // col group: cols tx*4..+3
    int ty = tid >> 5;     // row group: rows ty*4..+3 (warp-uniform -> broadcast)

    // acc2[c][p]: p=0 rows (0,1), p=1 rows (2,3) of this thread's 4x4 tile
    unsigned long long acc2[4][2];
    #pragma unroll
    for (int cJ = 0; cJ < 4; cJ++) { acc2[cJ][0] = 0ull; acc2[cJ][1] = 0ull; }

    #pragma unroll 8
    for (int k = 0; k < KSL; k++) {
        float4 a = As4[k][ty];
        float4 b = Bs4[k][tx];
        unsigned long long a01 = pack2(a.x, a.y);
        unsigned long long a23 = pack2(a.z, a.w);
        unsigned long long b0 = pack2(b.x, b.x);
        unsigned long long b1 = pack2(b.y, b.y);
        unsigned long long b2 = pack2(b.z, b.z);
        unsigned long long b3 = pack2(b.w, b.w);
        acc2[0][0] = fma2(a01, b0, acc2[0][0]);
        acc2[0][1] = fma2(a23, b0, acc2[0][1]);
        acc2[1][0] = fma2(a01, b1, acc2[1][0]);
        acc2[1][1] = fma2(a23, b1, acc2[1][1]);
        acc2[2][0] = fma2(a01, b2, acc2[2][0]);
        acc2[2][1] = fma2(a23, b2, acc2[2][1]);
        acc2[3][0] = fma2(a01, b3, acc2[3][0]);
        acc2[3][1] = fma2(a23, b3, acc2[3][1]);
    }

    float2 u00 = unpack2(acc2[0][0]), u01 = unpack2(acc2[0][1]);
    float2 u10 = unpack2(acc2[1][0]), u11 = unpack2(acc2[1][1]);
    float2 u20 = unpack2(acc2[2][0]), u21 = unpack2(acc2[2][1]);
    float2 u30 = unpack2(acc2[3][0]), u31 = unpack2(acc2[3][1]);

    float4* __restrict__ dst = (float4*)(&g_P2[blockIdx.y][0]);
    dst[(m0 + ty * 4 + 0) * (CC / 4) + tx] = make_float4(u00.x, u10.x, u20.x, u30.x);
    dst[(m0 + ty * 4 + 1) * (CC / 4) + tx] = make_float4(u00.y, u10.y, u20.y, u30.y);
    dst[(m0 + ty * 4 + 2) * (CC / 4) + tx] = make_float4(u01.x, u11.x, u21.x, u31.x);
    dst[(m0 + ty * 4 + 3) * (CC / 4) + tx] = make_float4(u01.y, u11.y, u21.y, u31.y);
}

// ---------------- K4: partial-sum reduce + loss + last-block final ------------
// grid 128 (a), 256 threads: tid<128 sums G1 row a, tid>=128 sums G2 row 128+a.
__global__ void __launch_bounds__(256) k_loss(float* __restrict__ out) {
    int a   = blockIdx.x;
    int tid = threadIdx.x;
    int b   = tid & 127;
    int m   = (tid >> 7) * CC + a;      // a (G1) or 128+a (G2)

    float G = 0.f;
    #pragma unroll
    for (int ks = 0; ks < KS; ks++) G += g_P2[ks][m * CC + b];

    __shared__ float sG[256];
    __shared__ float sred[128];
    sG[tid] = G;
    __syncthreads();

    if (tid < 128) {
        float G1 = sG[b];
        float G2 = sG[128 + b];
        float nRa = 0.f, nTa = 0.f, nMb = 0.f;
        #pragma unroll
        for (int y = 0; y < 4; y++) {
            nRa += g_nPart[y][0][a];
            nTa += g_nPart[y][1][a];
            nMb += g_nPart[y][2][b];
        }
        float sq1 = fmaxf(nRa + nMb - 2.f * G1, 1e-12f);
        float sq2 = fmaxf(nTa + nMb - 2.f * G2, 1e-12f);
        float wgt = (float)g_cnt[a] * (float)g_cnt[b];
        float term;
        if (a == b) {
            term = sq1 + sq2;       // label==1: clamped squared distance
        } else {
            term = 0.f;             // label==0: relu(0.5 - sq^(1/4))^2
            if (sq1 < 0.0625f) {
                float dd1 = sqrtf(sqrtf(sq1) + 1e-10f);
                float r1  = fmaxf(0.5f - dd1, 0.f);
                term += r1 * r1;
            }
            if (sq2 < 0.0625f) {
                float dd2 = sqrtf(sqrtf(sq2) + 1e-10f);
                float r2  = fmaxf(0.5f - dd2, 0.f);
                term += r2 * r2;
            }
        }
        sred[b] = wgt * term;
    }
    __syncthreads();
    for (int s = 64; s > 0; s >>= 1) {
        if (tid < s) sred[tid] += sred[tid + s];
        __syncthreads();
    }
    if (tid == 0) g_la[a] = sred[0];

    // last-block final reduce (threadFenceReduction pattern; deterministic)
    __shared__ int s_last;
    if (tid == 0) {
        __threadfence();
        int t = atomicAdd(&g_ctr, 1);
        s_last = (t == CC - 1) ? 1 : 0;
    }
    __syncthreads();
    if (s_last) {
        if (tid < 128) sred[tid] = g_la[tid];
        __syncthreads();
        for (int s = 64; s > 0; s >>= 1) {
            if (tid < s) sred[tid] += sred[tid + s];
            __syncthreads();
        }
        if (tid == 0) {
            out[0] = sred[0] * (1.0f / ((float)NN * (float)NN));
            g_ctr = 0;   // reset for next graph replay
        }
    }
}

// ---------------- launch ----------------
extern "C" void kernel_launch(void* const* d_in, const int* in_sizes, int n_in,
                              void* d_out, int out_size) {
    const float* m1 = (const float*)d_in[0];
    const float* m2 = (const float*)d_in[1];
    const int*   tg = (const int*)d_in[2];
    float* out = (float*)d_out;

    k_means<<<dim3(CC, 4), 128>>>(m1, m2, tg);
    k_T<<<dim3(DD / 32, CC / 32), 256>>>();
    k_gram<<<dim3(MTOT / MT, KS), 256>>>();
    k_loss<<<CC, 256>>>(out);
}

// round 7
// speedup vs baseline: 3.1264x; 1.0166x over previous
#include <cuda_runtime.h>

// Problem constants
#define NN   4096
#define DD   2048
#define CC   128
#define D4   (DD/4)          // 512 float4 per row
#define MTOT 256             // stacked rows: 0..127 = CR, 128..255 = CT
#define MT   32              // gram m-tile per block
#define KS   32              // k slices
#define KSL  64              // k per slice (KS*KSL == DD)

// ---------------- device scratch (no allocation allowed) ----------------
__device__ int   g_cnt[CC];
__device__ float g_C  [MTOT * DD];       // class means [m][k]: CR rows then CT rows
__device__ float g_Ct [DD * MTOT];       // transposed [k][m]   (2 MB)
__device__ float g_CMt[DD * CC];         // 0.5*(CR+CT) [k][c]  (1 MB)
__device__ float g_nPart[4][3][CC];      // per-col-quarter norm partials (R,T,M)
__device__ float g_P2[KS][MTOT * CC];    // Gram K-partials, fixed slots (4 MB)
__device__ float g_la2[2 * CC];          // per (half, class-row) loss partials
__device__ int   g_ctr = 0;              // last-block counter (self-resetting)

// ---------------- f32x2 helpers (FFMA2 path) ----------------
__device__ __forceinline__ unsigned long long pack2(float x, float y) {
    unsigned long long r;
    asm("mov.b64 %0, {%1, %2};" : "=l"(r) : "f"(x), "f"(y));
    return r;
}
__device__ __forceinline__ unsigned long long fma2(unsigned long long a,
                                                   unsigned long long b,
                                                   unsigned long long c) {
    unsigned long long d;
    asm("fma.rn.f32x2 %0, %1, %2, %3;" : "=l"(d) : "l"(a), "l"(b), "l"(c));
    return d;
}
__device__ __forceinline__ float2 unpack2(unsigned long long v) {
    float2 f;
    asm("mov.b64 {%0, %1}, %2;" : "=f"(f.x), "=f"(f.y) : "l"(v));
    return f;
}

// ---------------- K1: fused warp-scan classlist + per-class means + norms -----
// grid (CC, 4), 128 threads. Warp-local scans (no block syncs in the scan loop),
// then deterministic concat. Carries the mandatory 64MB read.
__global__ void __launch_bounds__(128) k_means(const float* __restrict__ m1,
                                               const float* __restrict__ m2,
                                               const int*   __restrict__ targets) {
    int c = blockIdx.x, y = blockIdx.y, tid = threadIdx.x;
    int lane = tid & 31, warp = tid >> 5;

    __shared__ int s_list[4][1024];   // per-warp candidate lists (worst-case safe)
    __shared__ int s_cnt[4];
    __shared__ int s_idx[NN];

    // warp w scans targets[w*1024 .. +1024) independently — no block barriers
    {
        int base = warp * 1024;
        int cntw = 0;
        unsigned lt = (1u << lane) - 1u;
        #pragma unroll 4
        for (int j = 0; j < 32; j++) {
            int i = base + j * 32 + lane;
            int t = targets[i];
            bool flag = (t == c);
            unsigned mask = __ballot_sync(0xffffffffu, flag);
            if (flag) s_list[warp][cntw + __popc(mask & lt)] = i;
            cntw += __popc(mask);
        }
        if (lane == 0) s_cnt[warp] = cntw;
    }
    __syncthreads();

    int cw0 = s_cnt[0], cw1 = s_cnt[1], cw2 = s_cnt[2], cw3 = s_cnt[3];
    int cnt = cw0 + cw1 + cw2 + cw3;
    if (cnt > NN) cnt = NN;
    {   // deterministic concat: warp w copies its list to its fixed offset
        int off = (warp > 0 ? cw0 : 0) + (warp > 1 ? cw1 : 0) + (warp > 2 ? cw2 : 0);
        int n = s_cnt[warp];
        for (int i = lane; i < n; i += 32) s_idx[off + i] = s_list[warp][i];
    }
    __syncthreads();

    // gather: this block owns 128 consecutive float4 columns
    int col4 = y * 128 + tid;     // 0..511
    const float4* __restrict__ m1v = (const float4*)m1;
    const float4* __restrict__ m2v = (const float4*)m2;

    float4 sR = make_float4(0.f, 0.f, 0.f, 0.f);
    float4 sT = make_float4(0.f, 0.f, 0.f, 0.f);
    int k = 0;
    for (; k + 8 <= cnt; k += 8) {
        #pragma unroll
        for (int u = 0; u < 8; u++) {
            int r = s_idx[k + u];
            float4 a = m1v[r * D4 + col4];
            float4 b = m2v[r * D4 + col4];
            sR.x += a.x; sR.y += a.y; sR.z += a.z; sR.w += a.w;
            sT.x += b.x; sT.y += b.y; sT.z += b.z; sT.w += b.w;
        }
    }
    for (; k < cnt; k++) {
        int r = s_idx[k];
        float4 a = m1v[r * D4 + col4];
        float4 b = m2v[r * D4 + col4];
        sR.x += a.x; sR.y += a.y; sR.z += a.z; sR.w += a.w;
        sT.x += b.x; sT.y += b.y; sT.z += b.z; sT.w += b.w;
    }

    float inv = 1.0f / (float)(cnt > 0 ? cnt : 1);
    float4 mr = make_float4(sR.x * inv, sR.y * inv, sR.z * inv, sR.w * inv);
    float4 mt = make_float4(sT.x * inv, sT.y * inv, sT.z * inv, sT.w * inv);
    float4 mm = make_float4(0.5f * (mr.x + mt.x), 0.5f * (mr.y + mt.y),
                            0.5f * (mr.z + mt.z), 0.5f * (mr.w + mt.w));

    ((float4*)g_C)[c * D4 + col4]        = mr;
    ((float4*)g_C)[(CC + c) * D4 + col4] = mt;

    // norm partials over this column quarter (fixed-tree reduce)
    float pR = mr.x * mr.x + mr.y * mr.y + mr.z * mr.z + mr.w * mr.w;
    float pT = mt.x * mt.x + mt.y * mt.y + mt.z * mt.z + mt.w * mt.w;
    float pM = mm.x * mm.x + mm.y * mm.y + mm.z * mm.z + mm.w * mm.w;
    __shared__ float r0[128], r1[128], r2[128];
    r0[tid] = pR; r1[tid] = pT; r2[tid] = pM;
    __syncthreads();
    for (int s = 64; s > 0; s >>= 1) {
        if (tid < s) { r0[tid] += r0[tid + s]; r1[tid] += r1[tid + s]; r2[tid] += r2[tid + s]; }
        __syncthreads();
    }
    if (tid == 0) {
        g_nPart[y][0][c] = r0[0];
        g_nPart[y][1][c] = r1[0];
        g_nPart[y][2][c] = r2[0];
        if (y == 0) g_cnt[c] = cnt;
    }
}

// ---------------- K2: paired-tile transpose; also emits CMt = 0.5(CR+CT) ------
// grid (DD/32 = 64 k-tiles, CC/32 = 4 m-pair-tiles), 256 threads.
__global__ void __launch_bounds__(256) k_T() {
    __shared__ float sR[32][33];
    __shared__ float sT[32][33];
    int kt = blockIdx.x, mt = blockIdx.y, tid = threadIdx.x;
    int mbase = mt * 32;

    const float4* __restrict__ c4 = (const float4*)g_C;
    int r  = tid >> 3;     // 0..31 (row within tile)
    int q4 = tid & 7;      // 0..7  (float4 within 32-float k window)
    float4 vR = c4[(mbase + r) * D4 + kt * 8 + q4];
    float4 vT = c4[(128 + mbase + r) * D4 + kt * 8 + q4];
    sR[r][q4 * 4 + 0] = vR.x; sR[r][q4 * 4 + 1] = vR.y;
    sR[r][q4 * 4 + 2] = vR.z; sR[r][q4 * 4 + 3] = vR.w;
    sT[r][q4 * 4 + 0] = vT.x; sT[r][q4 * 4 + 1] = vT.y;
    sT[r][q4 * 4 + 2] = vT.z; sT[r][q4 * 4 + 3] = vT.w;
    __syncthreads();

    int kk = tid >> 3;     // 0..31 (k within tile)
    int m4 = tid & 7;      // 0..7  (float4 of m)
    float4 wR = make_float4(sR[m4 * 4 + 0][kk], sR[m4 * 4 + 1][kk],
                            sR[m4 * 4 + 2][kk], sR[m4 * 4 + 3][kk]);
    float4 wT = make_float4(sT[m4 * 4 + 0][kk], sT[m4 * 4 + 1][kk],
                            sT[m4 * 4 + 2][kk], sT[m4 * 4 + 3][kk]);
    float4 wM = make_float4(0.5f * (wR.x + wT.x), 0.5f * (wR.y + wT.y),
                            0.5f * (wR.z + wT.z), 0.5f * (wR.w + wT.w));
    int krow = kt * 32 + kk;
    ((float4*)g_Ct)[krow * (MTOT / 4) + (mbase >> 2) + m4]         = wR;
    ((float4*)g_Ct)[krow * (MTOT / 4) + ((128 + mbase) >> 2) + m4] = wT;
    ((float4*)g_CMt)[krow * (CC / 4) + (mbase >> 2) + m4]          = wM;
}

// ---------------- K3: smem-tiled Gram with FFMA2: [256x128] = [CR;CT] * CmT ---
// grid (MTOT/MT = 8, KS = 32) = 256 blocks, 256 threads. 4x4 tile per thread,
// rows paired into f32x2 accumulators.
__global__ void __launch_bounds__(256) k_gram() {
    __shared__ float4 As4[KSL][9];     // [k][8 used], rows m0..m0+31
    __shared__ float4 Bs4[KSL][33];    // [k][32 used], all 128 cols

    int tid = threadIdx.x;
    int m0  = blockIdx.x * MT;
    int kb  = blockIdx.y * KSL;

    const float4* __restrict__ ct4 = (const float4*)g_Ct;
    #pragma unroll
    for (int i = 0; i < 2; i++) {
        int idx = tid + i * 256;            // 0..511
        int k = idx >> 3, j = idx & 7;
        As4[k][j] = ct4[(kb + k) * (MTOT / 4) + (m0 >> 2) + j];
    }
    const float4* __restrict__ cm4 = (const float4*)g_CMt;
    #pragma unroll
    for (int i = 0; i < 8; i++) {
        int idx = tid + i * 256;            // 0..2047
        int k = idx >> 5, q = idx & 31;
        Bs4[k][q] = cm4[(kb + k) * (CC / 4) + q];
    }
    __syncthreads();

    int tx = tid & 31;     // col group: cols tx*4..+3
    int ty = tid >> 5;     // row group: rows ty*4..+3 (warp-uniform -> broadcast)

    // acc2[c][p]: p=0 rows (0,1), p=1 rows (2,3) of this thread's 4x4 tile
    unsigned long long acc2[4][2];
    #pragma unroll
    for (int cJ = 0; cJ < 4; cJ++) { acc2[cJ][0] = 0ull; acc2[cJ][1] = 0ull; }

    #pragma unroll 8
    for (int k = 0; k < KSL; k++) {
        float4 a = As4[k][ty];
        float4 b = Bs4[k][tx];
        unsigned long long a01 = pack2(a.x, a.y);
        unsigned long long a23 = pack2(a.z, a.w);
        unsigned long long b0 = pack2(b.x, b.x);
        unsigned long long b1 = pack2(b.y, b.y);
        unsigned long long b2 = pack2(b.z, b.z);
        unsigned long long b3 = pack2(b.w, b.w);
        acc2[0][0] = fma2(a01, b0, acc2[0][0]);
        acc2[0][1] = fma2(a23, b0, acc2[0][1]);
        acc2[1][0] = fma2(a01, b1, acc2[1][0]);
        acc2[1][1] = fma2(a23, b1, acc2[1][1]);
        acc2[2][0] = fma2(a01, b2, acc2[2][0]);
        acc2[2][1] = fma2(a23, b2, acc2[2][1]);
        acc2[3][0] = fma2(a01, b3, acc2[3][0]);
        acc2[3][1] = fma2(a23, b3, acc2[3][1]);
    }

    float2 u00 = unpack2(acc2[0][0]), u01 = unpack2(acc2[0][1]);
    float2 u10 = unpack2(acc2[1][0]), u11 = unpack2(acc2[1][1]);
    float2 u20 = unpack2(acc2[2][0]), u21 = unpack2(acc2[2][1]);
    float2 u30 = unpack2(acc2[3][0]), u31 = unpack2(acc2[3][1]);

    float4* __restrict__ dst = (float4*)(&g_P2[blockIdx.y][0]);
    dst[(m0 + ty * 4 + 0) * (CC / 4) + tx] = make_float4(u00.x, u10.x, u20.x, u30.x);
    dst[(m0 + ty * 4 + 1) * (CC / 4) + tx] = make_float4(u00.y, u10.y, u20.y, u30.y);
    dst[(m0 + ty * 4 + 2) * (CC / 4) + tx] = make_float4(u01.x, u11.x, u21.x, u31.x);
    dst[(m0 + ty * 4 + 3) * (CC / 4) + tx] = make_float4(u01.y, u11.y, u21.y, u31.y);
}

// ---------------- K4: half-split loss + forced-MLP partial reduce -------------
// grid (CC, 2), 128 threads. Block (a, 0): CR half-terms for row a;
// block (a, 1): CT half-terms. Loss is additive across halves (even on the
// diagonal: term = sq1 + sq2), so halves sum independently.
__global__ void __launch_bounds__(128) k_loss(float* __restrict__ out) {
    int a    = blockIdx.x;
    int half = blockIdx.y;          // 0 = CR(G1), 1 = CT(G2)
    int b    = threadIdx.x;         // one b per thread
    int m    = half * CC + a;

    // stage all KS partials in registers first -> forces MLP=32 batched loads
    float v[KS];
    #pragma unroll
    for (int ks = 0; ks < KS; ks++) v[ks] = g_P2[ks][m * CC + b];
    float G = 0.f;
    #pragma unroll
    for (int ks = 0; ks < KS; ks++) G += v[ks];

    float nA = 0.f, nMb = 0.f;      // half-selected row norm + Cm col norm
    #pragma unroll
    for (int y = 0; y < 4; y++) {
        nA  += g_nPart[y][half][a];   // [0]=R norms, [1]=T norms
        nMb += g_nPart[y][2][b];
    }

    float sq  = fmaxf(nA + nMb - 2.f * G, 1e-12f);
    float wgt = (float)g_cnt[a] * (float)g_cnt[b];
    float term;
    if (a == b) {
        term = sq;                  // label==1 half-term: clamped squared dist
    } else {
        term = 0.f;                 // label==0 half-term: relu(0.5 - sq^(1/4))^2
        if (sq < 0.0625f) {
            float dd = sqrtf(sqrtf(sq) + 1e-10f);
            float r  = fmaxf(0.5f - dd, 0.f);
            term = r * r;
        }
    }

    __shared__ float sred[128];
    sred[b] = wgt * term;
    __syncthreads();
    for (int s = 64; s > 0; s >>= 1) {
        if (b < s) sred[b] += sred[b + s];
        __syncthreads();
    }
    if (b == 0) g_la2[half * CC + a] = sred[0];

    // last-block final reduce over 256 partials (deterministic fixed order)
    __shared__ int s_last;
    if (b == 0) {
        __threadfence();
        int t = atomicAdd(&g_ctr, 1);
        s_last = (t == 2 * CC - 1) ? 1 : 0;
    }
    __syncthreads();
    if (s_last) {
        sred[b] = g_la2[b] + g_la2[CC + b];
        __syncthreads();
        for (int s = 64; s > 0; s >>= 1) {
            if (b < s) sred[b] += sred[b + s];
            __syncthreads();
        }
        if (b == 0) {
            out[0] = sred[0] * (1.0f / ((float)NN * (float)NN));
            g_ctr = 0;   // reset for next graph replay
        }
    }
}

// ---------------- launch ----------------
extern "C" void kernel_launch(void* const* d_in, const int* in_sizes, int n_in,
                              void* d_out, int out_size) {
    const float* m1 = (const float*)d_in[0];
    const float* m2 = (const float*)d_in[1];
    const int*   tg = (const int*)d_in[2];
    float* out = (float*)d_out;

    k_means<<<dim3(CC, 4), 128>>>(m1, m2, tg);
    k_T<<<dim3(DD / 32, CC / 32), 256>>>();
    k_gram<<<dim3(MTOT / MT, KS), 256>>>();
    k_loss<<<dim3(CC, 2), 128>>>(out);
}